// round 15
// baseline (speedup 1.0000x reference)
#include <cuda_runtime.h>
#include <cuda_bf16.h>
#include <cstdint>
#include <math.h>

#define B_   2
#define T_   2048
#define DM_  512
#define H_   8
#define D_   64
#define BH_  (B_*H_)
#define U_   3      // int(0.4 * ln(2048)) = 3 selected queries per (b,h)
#define KC_  2      // k-split for kl kernel
#define NCH_ 8      // key-chunk split for sparse attention

// ---------------- scratch (static device allocations; no cudaMalloc) ----------------
__device__ float g_Q[B_*T_*DM_];          // projected Q fp32
__device__ float g_K[B_*T_*DM_];
__device__ float g_V[B_*T_*DM_];
__device__ __nv_bfloat16 g_Qh[B_*T_*DM_]; // bf16 copies for tensor-core KL
__device__ __nv_bfloat16 g_Kh[B_*T_*DM_];
__device__ float g_Zp[KC_*BH_*T_];        // partial Z = sum exp(s)
__device__ float g_Sp[KC_*BH_*T_];        // partial S (scaled back from log2 domain)
__device__ int   g_top[BH_*U_];
__device__ float g_attp[BH_*U_*NCH_*D_];
__device__ float g_zc[BH_*U_*NCH_];

__device__ __forceinline__ void mma_bf16(float* c, const unsigned* a, const unsigned* b) {
    asm volatile(
        "mma.sync.aligned.m16n8k16.row.col.f32.bf16.bf16.f32 "
        "{%0,%1,%2,%3}, {%4,%5,%6,%7}, {%8,%9}, {%0,%1,%2,%3};"
        : "+f"(c[0]), "+f"(c[1]), "+f"(c[2]), "+f"(c[3])
        : "r"(a[0]), "r"(a[1]), "r"(a[2]), "r"(a[3]), "r"(b[0]), "r"(b[1]));
}
// C = 0 variant: overwrites accumulators (no zeroing movs needed)
__device__ __forceinline__ void mma_bf16_z(float* c, const unsigned* a, const unsigned* b) {
    asm volatile(
        "mma.sync.aligned.m16n8k16.row.col.f32.bf16.bf16.f32 "
        "{%0,%1,%2,%3}, {%4,%5,%6,%7}, {%8,%9}, {%10,%10,%10,%10};"
        : "=f"(c[0]), "=f"(c[1]), "=f"(c[2]), "=f"(c[3])
        : "r"(a[0]), "r"(a[1]), "r"(a[2]), "r"(a[3]), "r"(b[0]), "r"(b[1]), "f"(0.f));
}
__device__ __forceinline__ unsigned smem_u32(const void* p) {
    unsigned a;
    asm("{ .reg .u64 t; cvta.to.shared.u64 t, %1; cvt.u32.u64 %0, t; }" : "=r"(a) : "l"(p));
    return a;
}
__device__ __forceinline__ void ldmx4(unsigned& r0, unsigned& r1, unsigned& r2, unsigned& r3,
                                      unsigned addr) {
    asm volatile("ldmatrix.sync.aligned.m8n8.x4.shared.b16 {%0,%1,%2,%3}, [%4];"
                 : "=r"(r0), "=r"(r1), "=r"(r2), "=r"(r3) : "r"(addr));
}
__device__ __forceinline__ void cp16(unsigned dst, const void* src) {
    asm volatile("cp.async.ca.shared.global [%0], [%1], 16;" :: "r"(dst), "l"(src));
}
__device__ __forceinline__ void cp_commit()  { asm volatile("cp.async.commit_group;" ::: "memory"); }
__device__ __forceinline__ void cp_wait1()   { asm volatile("cp.async.wait_group 1;" ::: "memory"); }
__device__ __forceinline__ void cp_wait0()   { asm volatile("cp.async.wait_group 0;" ::: "memory"); }

// 2^t on the FMA pipe (no MUFU): magic-number split t = i + f, |f| <= 0.5,
// degree-5 Taylor for 2^f (rel err ~2e-6), exponent add via int bits.
__device__ __forceinline__ float exp2_fma(float t) {
    float z = t + 12582912.0f;                    // 1.5 * 2^23
    float r = z - 12582912.0f;                    // round(t)
    float f = t - r;                              // frac, [-0.5, 0.5]
    float p = fmaf(1.3333558e-3f, f, 9.6181291e-3f);
    p = fmaf(p, f, 5.5504109e-2f);
    p = fmaf(p, f, 2.4022651e-1f);
    p = fmaf(p, f, 6.9314718e-1f);
    p = fmaf(p, f, 1.0f);
    int i = (__float_as_int(z) - 0x4B400000) << 23;
    return __int_as_float(__float_as_int(p) + i);
}

// insert (nv,ni) into a sorted top-3 list; ties -> lower index (jax top_k)
__device__ __forceinline__ void ins3(float* v, int* ix, float nv, int ni) {
    if (nv > v[0] || (nv == v[0] && ni < ix[0])) {
        v[2] = v[1]; ix[2] = ix[1];
        v[1] = v[0]; ix[1] = ix[0];
        v[0] = nv;   ix[0] = ni;
    } else if (nv > v[1] || (nv == v[1] && ni < ix[1])) {
        v[2] = v[1]; ix[2] = ix[1];
        v[1] = nv;   ix[1] = ni;
    } else if (nv > v[2] || (nv == v[2] && ni < ix[2])) {
        v[2] = nv;   ix[2] = ni;
    }
}

// =====================================================================
// Fused projection GEMMs via split-bf16 HMMA (3-pass: hh + hl + lh),
// in-kernel hi/lo conversion; next-tile global loads overlapped with MMA.
// =====================================================================
__global__ __launch_bounds__(256) void proj3_kernel(
    const float* __restrict__ q,  const float* __restrict__ k,  const float* __restrict__ v,
    const float* __restrict__ Wq, const float* __restrict__ Wk, const float* __restrict__ Wv,
    const float* __restrict__ bq, const float* __restrict__ bk, const float* __restrict__ bv,
    float* __restrict__ Qp, float* __restrict__ Kp, float* __restrict__ Vp)
{
    const float* X; const float* W; const float* bias; float* Y; __nv_bfloat16* Yh;
    if (blockIdx.z == 0)      { X = q; W = Wq; bias = bq; Y = Qp; Yh = g_Qh; }
    else if (blockIdx.z == 1) { X = k; W = Wk; bias = bk; Y = Kp; Yh = g_Kh; }
    else                      { X = v; W = Wv; bias = bv; Y = Vp; Yh = 0; }

    __shared__ __nv_bfloat16 Xh[128][40], Xl[128][40];   // [row][k], +8 pad
    __shared__ __nv_bfloat16 Wh[128][40], Wl[128][40];

    const int m0 = blockIdx.x * 128;
    const int n0 = blockIdx.y * 128;
    const int tid = threadIdx.x;
    const int w = tid >> 5, l = tid & 31;
    const int g = l >> 2, tg = l & 3;
    const int wm = w >> 2;
    const int wn = w & 3;
    const int lr = tid >> 1;
    const int lcb = (tid & 1) * 16;

    float acc[4][4][4];
#pragma unroll
    for (int mi = 0; mi < 4; mi++)
#pragma unroll
        for (int ni = 0; ni < 4; ni++)
#pragma unroll
            for (int j = 0; j < 4; j++) acc[mi][ni][j] = 0.f;

    float4 xv[4], wv[4];
#pragma unroll
    for (int c = 0; c < 4; c++) {
        xv[c] = *(const float4*)&X[(size_t)(m0 + lr) * DM_ + lcb + c * 4];
        wv[c] = *(const float4*)&W[(size_t)(n0 + lr) * DM_ + lcb + c * 4];
    }

    for (int kt = 0; kt < DM_; kt += 32) {
        __syncthreads();   // prev tile's MMA consumers done
#pragma unroll
        for (int c = 0; c < 4; c++) {
            const int idx = lcb + c * 4;
            float xs[4] = {xv[c].x, xv[c].y, xv[c].z, xv[c].w};
            float ws[4] = {wv[c].x, wv[c].y, wv[c].z, wv[c].w};
            __nv_bfloat16 xh[4], wh[4];
            float xr[4], wr[4];
#pragma unroll
            for (int e = 0; e < 4; e++) {
                xh[e] = __float2bfloat16(xs[e]);
                xr[e] = xs[e] - __bfloat162float(xh[e]);
                wh[e] = __float2bfloat16(ws[e]);
                wr[e] = ws[e] - __bfloat162float(wh[e]);
            }
            *(__nv_bfloat162*)&Xh[lr][idx]     = __nv_bfloat162(xh[0], xh[1]);
            *(__nv_bfloat162*)&Xh[lr][idx + 2] = __nv_bfloat162(xh[2], xh[3]);
            *(__nv_bfloat162*)&Xl[lr][idx]     = __floats2bfloat162_rn(xr[0], xr[1]);
            *(__nv_bfloat162*)&Xl[lr][idx + 2] = __floats2bfloat162_rn(xr[2], xr[3]);
            *(__nv_bfloat162*)&Wh[lr][idx]     = __nv_bfloat162(wh[0], wh[1]);
            *(__nv_bfloat162*)&Wh[lr][idx + 2] = __nv_bfloat162(wh[2], wh[3]);
            *(__nv_bfloat162*)&Wl[lr][idx]     = __floats2bfloat162_rn(wr[0], wr[1]);
            *(__nv_bfloat162*)&Wl[lr][idx + 2] = __floats2bfloat162_rn(wr[2], wr[3]);
        }
        __syncthreads();

        // issue next tile's global loads (overlap with MMA below)
        if (kt + 32 < DM_) {
#pragma unroll
            for (int c = 0; c < 4; c++) {
                xv[c] = *(const float4*)&X[(size_t)(m0 + lr) * DM_ + kt + 32 + lcb + c * 4];
                wv[c] = *(const float4*)&W[(size_t)(n0 + lr) * DM_ + kt + 32 + lcb + c * 4];
            }
        }

#pragma unroll
        for (int ks = 0; ks < 2; ks++) {
            const int k0 = ks * 16;
            unsigned ah[4][4], al[4][4];
#pragma unroll
            for (int mi = 0; mi < 4; mi++) {
                const int r0 = wm * 64 + mi * 16 + g, r1 = r0 + 8;
                ah[mi][0] = *(const unsigned*)&Xh[r0][k0 + tg * 2];
                ah[mi][1] = *(const unsigned*)&Xh[r1][k0 + tg * 2];
                ah[mi][2] = *(const unsigned*)&Xh[r0][k0 + tg * 2 + 8];
                ah[mi][3] = *(const unsigned*)&Xh[r1][k0 + tg * 2 + 8];
                al[mi][0] = *(const unsigned*)&Xl[r0][k0 + tg * 2];
                al[mi][1] = *(const unsigned*)&Xl[r1][k0 + tg * 2];
                al[mi][2] = *(const unsigned*)&Xl[r0][k0 + tg * 2 + 8];
                al[mi][3] = *(const unsigned*)&Xl[r1][k0 + tg * 2 + 8];
            }
            unsigned bh[4][2], bl[4][2];
#pragma unroll
            for (int ni = 0; ni < 4; ni++) {
                const int col = wn * 32 + ni * 8 + g;
                bh[ni][0] = *(const unsigned*)&Wh[col][k0 + tg * 2];
                bh[ni][1] = *(const unsigned*)&Wh[col][k0 + tg * 2 + 8];
                bl[ni][0] = *(const unsigned*)&Wl[col][k0 + tg * 2];
                bl[ni][1] = *(const unsigned*)&Wl[col][k0 + tg * 2 + 8];
            }
#pragma unroll
            for (int mi = 0; mi < 4; mi++)
#pragma unroll
                for (int ni = 0; ni < 4; ni++) {
                    mma_bf16(acc[mi][ni], ah[mi], bh[ni]);
                    mma_bf16(acc[mi][ni], ah[mi], bl[ni]);
                    mma_bf16(acc[mi][ni], al[mi], bh[ni]);
                }
        }
    }

#pragma unroll
    for (int ni = 0; ni < 4; ni++) {
        const int col = n0 + wn * 32 + ni * 8 + tg * 2;
        const float b0 = bias[col], b1 = bias[col + 1];
#pragma unroll
        for (int mi = 0; mi < 4; mi++) {
            const int row0 = m0 + wm * 64 + mi * 16 + g, row1 = row0 + 8;
            float o00 = acc[mi][ni][0] + b0, o01 = acc[mi][ni][1] + b1;
            float o10 = acc[mi][ni][2] + b0, o11 = acc[mi][ni][3] + b1;
            *(float2*)&Y[(size_t)row0 * DM_ + col] = make_float2(o00, o01);
            *(float2*)&Y[(size_t)row1 * DM_ + col] = make_float2(o10, o11);
            if (Yh) {
                *(__nv_bfloat162*)&Yh[(size_t)row0 * DM_ + col] = __floats2bfloat162_rn(o00, o01);
                *(__nv_bfloat162*)&Yh[(size_t)row1 * DM_ + col] = __floats2bfloat162_rn(o10, o11);
            }
        }
    }
}

// =====================================================================
// KL via HMMA + ldmatrix + cp.async double-buffered K tiles.
// Epilogue exp computed on the FMA pipe (exp2_fma) — no MUFU.
// t = acc*0.125*log2e; e = 2^t; Z += e; S' += e*t; final S = S'*ln2.
// =====================================================================
__global__ __launch_bounds__(256) void kl_hmma_kernel()
{
    extern __shared__ __align__(16) char smraw[];
    const unsigned smb = smem_u32(smraw);
    const unsigned QSB = smb;
    const unsigned KSB0 = smb + 18432u, KSB1 = smb + 36864u;

    const int tid = threadIdx.x;
    const int w = tid >> 5, l = tid & 31;
    const int g = l >> 2, tg = l & 3;
    const int bh = blockIdx.x, b = bh >> 3, h = bh & 7;
    const int q0 = blockIdx.y * 128;
    const int kc = blockIdx.z, kbase = kc * (T_ / KC_);
    const int NT = (T_ / KC_) / 128;   // 8 key tiles

    const __nv_bfloat16* Qh = g_Qh + (size_t)(b * T_) * DM_ + h * D_;
    const __nv_bfloat16* Kh = g_Kh + (size_t)(b * T_) * DM_ + h * D_;

    const int cr = tid >> 1, chalf = tid & 1;
    const unsigned cdst_off = (unsigned)(cr * 144 + chalf * 64);

    {
        const __nv_bfloat16* src = Qh + (size_t)(q0 + cr) * DM_ + chalf * 32;
#pragma unroll
        for (int c = 0; c < 4; c++) cp16(QSB + cdst_off + c * 16, src + c * 8);
        const __nv_bfloat16* ksrc = Kh + (size_t)(kbase + cr) * DM_ + chalf * 32;
#pragma unroll
        for (int c = 0; c < 4; c++) cp16(KSB0 + cdst_off + c * 16, ksrc + c * 8);
        cp_commit();
    }
    {
        const __nv_bfloat16* ksrc = Kh + (size_t)(kbase + 128 + cr) * DM_ + chalf * 32;
#pragma unroll
        for (int c = 0; c < 4; c++) cp16(KSB1 + cdst_off + c * 16, ksrc + c * 8);
        cp_commit();
    }

    float acc[16][4];
    float Z0 = 0.f, S0 = 0.f, Z1 = 0.f, S1 = 0.f;
    const float C1 = 0.125f * 1.4426950408889634f;   // scale * log2(e)

    const unsigned a_row_off = (unsigned)((w * 16 + (l & 15)) * 144 + ((l >> 4) << 3) * 2);
    const unsigned b_row_off = (unsigned)((((l >> 4) << 3) + (l & 7)) * 144 + (((l >> 3) & 1) << 3) * 2);

    for (int it = 0; it < NT; it++) {
        if (it + 1 < NT) cp_wait1(); else cp_wait0();
        __syncthreads();

        const unsigned kb = (it & 1) ? KSB1 : KSB0;
#pragma unroll
        for (int ks = 0; ks < 4; ks++) {
            const unsigned k0b = (unsigned)(ks * 32);
            unsigned a[4];
            ldmx4(a[0], a[1], a[2], a[3], QSB + a_row_off + k0b);
#pragma unroll
            for (int nb = 0; nb < 8; nb++) {
                unsigned b0, b1, b2, b3;
                ldmx4(b0, b1, b2, b3, kb + b_row_off + (unsigned)(nb * 16 * 144) + k0b);
                unsigned bb0[2] = {b0, b1}, bb1[2] = {b2, b3};
                if (ks == 0) {
                    mma_bf16_z(acc[nb * 2],     a, bb0);
                    mma_bf16_z(acc[nb * 2 + 1], a, bb1);
                } else {
                    mma_bf16(acc[nb * 2],     a, bb0);
                    mma_bf16(acc[nb * 2 + 1], a, bb1);
                }
            }
        }

        // epilogue: exp on the FMA pipe
#pragma unroll
        for (int ni = 0; ni < 16; ni++) {
            float t0 = acc[ni][0] * C1; float e0 = exp2_fma(t0); Z0 += e0; S0 += e0 * t0;
            float t1 = acc[ni][1] * C1; float e1 = exp2_fma(t1); Z0 += e1; S0 += e1 * t1;
            float t2 = acc[ni][2] * C1; float e2 = exp2_fma(t2); Z1 += e2; S1 += e2 * t2;
            float t3 = acc[ni][3] * C1; float e3 = exp2_fma(t3); Z1 += e3; S1 += e3 * t3;
        }
        __syncthreads();   // buffer (it&1) fully consumed by all warps

        if (it + 2 < NT) {
            const unsigned dst = ((it & 1) ? KSB1 : KSB0) + cdst_off;
            const __nv_bfloat16* ksrc = Kh + (size_t)(kbase + (it + 2) * 128 + cr) * DM_ + chalf * 32;
#pragma unroll
            for (int c = 0; c < 4; c++) cp16(dst + c * 16, ksrc + c * 8);
            cp_commit();
        }
    }

#pragma unroll
    for (int off = 1; off < 4; off <<= 1) {
        Z0 += __shfl_xor_sync(0xffffffffu, Z0, off);
        S0 += __shfl_xor_sync(0xffffffffu, S0, off);
        Z1 += __shfl_xor_sync(0xffffffffu, Z1, off);
        S1 += __shfl_xor_sync(0xffffffffu, S1, off);
    }
    if (tg == 0) {
        const float LN2 = 0.6931471805599453f;
        const int base = (kc * BH_ + bh) * T_ + q0 + w * 16 + g;
        g_Zp[base]     = Z0;  g_Sp[base]     = S0 * LN2;
        g_Zp[base + 8] = Z1;  g_Sp[base + 8] = S1 * LN2;
    }
}

// =====================================================================
// Top-3 per (b,h), single pass: per-thread top-3 of 8 elems, 5 shfl
// merge rounds per warp, one smem stage, serial merge of 8 lists.
// =====================================================================
__global__ __launch_bounds__(256) void topk_kernel()
{
    __shared__ float swv[8][3];
    __shared__ int   swi[8][3];
    const int bh = blockIdx.x;
    const int tid = threadIdx.x;
    const int lane = tid & 31, warp = tid >> 5;
    const float LOGU = logf(1.0f / (float)T_ + 1e-10f);

    float v[3] = {-1e30f, -1e30f, -1e30f};
    int ix[3] = {T_, T_, T_};
#pragma unroll
    for (int kk = 0; kk < 8; kk++) {
        const int i = kk * 256 + tid;
        float z = g_Zp[bh * T_ + i] + g_Zp[(BH_ + bh) * T_ + i];
        float s = g_Sp[bh * T_ + i] + g_Sp[(BH_ + bh) * T_ + i];
        float kl = s / z - __logf(z) - LOGU;
        ins3(v, ix, kl, i);
    }
#pragma unroll
    for (int off = 16; off > 0; off >>= 1) {
        float ov[3]; int oix[3];
#pragma unroll
        for (int j = 0; j < 3; j++) {
            ov[j]  = __shfl_xor_sync(0xffffffffu, v[j], off);
            oix[j] = __shfl_xor_sync(0xffffffffu, ix[j], off);
        }
#pragma unroll
        for (int j = 0; j < 3; j++) ins3(v, ix, ov[j], oix[j]);
    }
    if (lane == 0) {
#pragma unroll
        for (int j = 0; j < 3; j++) { swv[warp][j] = v[j]; swi[warp][j] = ix[j]; }
    }
    __syncthreads();
    if (tid == 0) {
        float bv[3] = {-1e30f, -1e30f, -1e30f};
        int bix[3] = {T_, T_, T_};
        for (int wq = 0; wq < 8; wq++)
#pragma unroll
            for (int j = 0; j < 3; j++) ins3(bv, bix, swv[wq][j], swi[wq][j]);
#pragma unroll
        for (int r = 0; r < U_; r++) g_top[bh * U_ + r] = bix[r];
    }
}

// =====================================================================
// Reduced attention (fp32 path): grid (48, NCH_).
// =====================================================================
__global__ __launch_bounds__(256) void sparse_attn_kernel()
{
    __shared__ float qs[64];
    __shared__ float e[256];
    __shared__ float red[8];
    __shared__ float pb[4][64];

    const int bid = blockIdx.x;
    const int ch  = blockIdx.y;
    const int bh = bid / U_;
    const int b = bh >> 3, h = bh & 7;
    const int t = g_top[bid];
    const int tid = threadIdx.x;
    const int warp = tid >> 5, lane = tid & 31;

    const float* Qb = g_Q + ((size_t)(b * T_) + t) * DM_ + h * D_;
    if (tid < 16) *(float4*)&qs[tid * 4] = *(const float4*)&Qb[tid * 4];
    __syncthreads();

    const int kk = ch * 256 + tid;
    const float* Krow = g_K + ((size_t)(b * T_) + kk) * DM_ + h * D_;
    float dot = 0.f;
#pragma unroll
    for (int i = 0; i < 16; i++) {
        float4 kv = *(const float4*)&Krow[i * 4];
        float4 qv = *(const float4*)&qs[i * 4];
        dot += kv.x * qv.x + kv.y * qv.y + kv.z * qv.z + kv.w * qv.w;
    }
    float s = dot * 0.125f;
    if (!(s == s)) s = -10000.f;
    s = fminf(fmaxf(s, -10000.f), 10000.f);
    float ev = expf(s);
    e[tid] = ev;

    float zr = ev;
#pragma unroll
    for (int off = 16; off > 0; off >>= 1) zr += __shfl_xor_sync(0xffffffffu, zr, off);
    if (lane == 0) red[warp] = zr;
    __syncthreads();
    if (tid == 0) {
        float z = 0.f;
        for (int w = 0; w < 8; w++) z += red[w];
        g_zc[bid * NCH_ + ch] = z;
    }

    const int d = tid & 63, c = tid >> 6;
    const float* Vb = g_V + ((size_t)(b * T_) + ch * 256 + c * 64) * DM_ + h * D_ + d;
    float o = 0.f;
#pragma unroll 8
    for (int j = 0; j < 64; j++) o += e[c * 64 + j] * Vb[(size_t)j * DM_];
    pb[c][d] = o;
    __syncthreads();
    if (tid < 64)
        g_attp[(bid * NCH_ + ch) * D_ + tid] =
            pb[0][tid] + pb[1][tid] + pb[2][tid] + pb[3][tid];
}

// =====================================================================
// Output: fill with bo, then add the 48 selected-row contributions.
// =====================================================================
__global__ void init_out_kernel(float* __restrict__ out, const float* __restrict__ bo)
{
    int idx = blockIdx.x * 256 + threadIdx.x;
    if (idx < B_ * T_ * DM_) out[idx] = bo[idx & (DM_ - 1)];
}

__global__ __launch_bounds__(512) void scatter_kernel(
    const float* __restrict__ Wo, float* __restrict__ out)
{
    __shared__ float att[64];
    const int bid = blockIdx.x;
    const int bh = bid / U_;
    const int b = bh >> 3, h = bh & 7;
    const int t = g_top[bid];
    const int j = threadIdx.x;
    if (j < 64) {
        float z = 0.f, o = 0.f;
#pragma unroll
        for (int c = 0; c < NCH_; c++) {
            z += g_zc[bid * NCH_ + c];
            o += g_attp[(bid * NCH_ + c) * D_ + j];
        }
        att[j] = o / z;
    }
    __syncthreads();
    const float* w = Wo + (size_t)j * DM_ + h * D_;
    float a = 0.f;
#pragma unroll
    for (int d = 0; d < 64; d++) a += att[d] * w[d];
    atomicAdd(&out[((size_t)b * T_ + t) * DM_ + j], a);
}

// =====================================================================
extern "C" void kernel_launch(void* const* d_in, const int* in_sizes, int n_in,
                              void* d_out, int out_size)
{
    const float* query = (const float*)d_in[0];
    const float* key   = (const float*)d_in[1];
    const float* value = (const float*)d_in[2];
    const float* Wq    = (const float*)d_in[3];
    const float* bq    = (const float*)d_in[4];
    const float* Wk    = (const float*)d_in[5];
    const float* bk    = (const float*)d_in[6];
    const float* Wv    = (const float*)d_in[7];
    const float* bv    = (const float*)d_in[8];
    const float* Wo    = (const float*)d_in[9];
    const float* bo    = (const float*)d_in[10];
    float* out = (float*)d_out;

    float *Qp, *Kp, *Vp;
    cudaGetSymbolAddress((void**)&Qp, g_Q);
    cudaGetSymbolAddress((void**)&Kp, g_K);
    cudaGetSymbolAddress((void**)&Vp, g_V);

    const int KL_SMEM = 3 * 18432;  // 55296
    cudaFuncSetAttribute(kl_hmma_kernel, cudaFuncAttributeMaxDynamicSharedMemorySize, KL_SMEM);

    dim3 pg(32, 4, 3);
    proj3_kernel<<<pg, 256>>>(query, key, value, Wq, Wk, Wv, bq, bk, bv, Qp, Kp, Vp);

    dim3 kg(BH_, T_ / 128, KC_);  // (16, 16, 2)
    kl_hmma_kernel<<<kg, 256, KL_SMEM>>>();

    topk_kernel<<<BH_, 256>>>();

    dim3 sg(BH_ * U_, NCH_);
    sparse_attn_kernel<<<sg, 256>>>();

    init_out_kernel<<<(B_ * T_ * DM_ + 255) / 256, 256>>>(out, bo);
    scatter_kernel<<<BH_ * U_, 512>>>(Wo, out);
}

// round 16
// speedup vs baseline: 1.1254x; 1.1254x over previous
#include <cuda_runtime.h>
#include <cuda_bf16.h>
#include <cstdint>
#include <math.h>

#define B_   2
#define T_   2048
#define DM_  512
#define H_   8
#define D_   64
#define BH_  (B_*H_)
#define U_   3      // int(0.4 * ln(2048)) = 3 selected queries per (b,h)
#define KC_  2      // k-split for kl kernel
#define NCH_ 8      // key-chunk split for sparse attention

// ---------------- scratch (static device allocations; no cudaMalloc) ----------------
__device__ float g_Q[B_*T_*DM_];          // projected Q fp32
__device__ float g_K[B_*T_*DM_];
__device__ float g_V[B_*T_*DM_];
__device__ __nv_bfloat16 g_Qh[B_*T_*DM_]; // bf16 copies for tensor-core KL
__device__ __nv_bfloat16 g_Kh[B_*T_*DM_];
__device__ float g_Zp[KC_*BH_*T_];        // partial Z = sum exp(s)
__device__ float g_Sp[KC_*BH_*T_];        // partial S = sum exp(s)*s
__device__ int   g_top[BH_*U_];
__device__ float g_attp[BH_*U_*NCH_*D_];
__device__ float g_zc[BH_*U_*NCH_];

__device__ __forceinline__ void mma_bf16(float* c, const unsigned* a, const unsigned* b) {
    asm volatile(
        "mma.sync.aligned.m16n8k16.row.col.f32.bf16.bf16.f32 "
        "{%0,%1,%2,%3}, {%4,%5,%6,%7}, {%8,%9}, {%0,%1,%2,%3};"
        : "+f"(c[0]), "+f"(c[1]), "+f"(c[2]), "+f"(c[3])
        : "r"(a[0]), "r"(a[1]), "r"(a[2]), "r"(a[3]), "r"(b[0]), "r"(b[1]));
}
__device__ __forceinline__ unsigned smem_u32(const void* p) {
    unsigned a;
    asm("{ .reg .u64 t; cvta.to.shared.u64 t, %1; cvt.u32.u64 %0, t; }" : "=r"(a) : "l"(p));
    return a;
}
__device__ __forceinline__ void ldmx4(unsigned& r0, unsigned& r1, unsigned& r2, unsigned& r3,
                                      unsigned addr) {
    asm volatile("ldmatrix.sync.aligned.m8n8.x4.shared.b16 {%0,%1,%2,%3}, [%4];"
                 : "=r"(r0), "=r"(r1), "=r"(r2), "=r"(r3) : "r"(addr));
}
__device__ __forceinline__ void cp16(unsigned dst, const void* src) {
    asm volatile("cp.async.ca.shared.global [%0], [%1], 16;" :: "r"(dst), "l"(src));
}
__device__ __forceinline__ void cp_commit()  { asm volatile("cp.async.commit_group;" ::: "memory"); }
__device__ __forceinline__ void cp_wait1()   { asm volatile("cp.async.wait_group 1;" ::: "memory"); }
__device__ __forceinline__ void cp_wait0()   { asm volatile("cp.async.wait_group 0;" ::: "memory"); }
// insert (nv,ni) into a sorted top-3 list; ties -> lower index (jax top_k)
__device__ __forceinline__ void ins3(float* v, int* ix, float nv, int ni) {
    if (nv > v[0] || (nv == v[0] && ni < ix[0])) {
        v[2] = v[1]; ix[2] = ix[1];
        v[1] = v[0]; ix[1] = ix[0];
        v[0] = nv;   ix[0] = ni;
    } else if (nv > v[1] || (nv == v[1] && ni < ix[1])) {
        v[2] = v[1]; ix[2] = ix[1];
        v[1] = nv;   ix[1] = ni;
    } else if (nv > v[2] || (nv == v[2] && ni < ix[2])) {
        v[2] = nv;   ix[2] = ni;
    }
}

// =====================================================================
// Fused projection GEMMs via split-bf16 HMMA (3-pass: hh + hl + lh),
// in-kernel hi/lo conversion (byte-exact R12 mainloop). The V branch
// (z==2) additionally fills out[] with bo (replaces init_out_kernel;
// the (32,4) tile grid covers out exactly once).
// =====================================================================
__global__ __launch_bounds__(256) void proj3_kernel(
    const float* __restrict__ q,  const float* __restrict__ k,  const float* __restrict__ v,
    const float* __restrict__ Wq, const float* __restrict__ Wk, const float* __restrict__ Wv,
    const float* __restrict__ bq, const float* __restrict__ bk, const float* __restrict__ bv,
    float* __restrict__ Qp, float* __restrict__ Kp, float* __restrict__ Vp,
    const float* __restrict__ bo, float* __restrict__ out)
{
    const float* X; const float* W; const float* bias; float* Y; __nv_bfloat16* Yh;
    if (blockIdx.z == 0)      { X = q; W = Wq; bias = bq; Y = Qp; Yh = g_Qh; }
    else if (blockIdx.z == 1) { X = k; W = Wk; bias = bk; Y = Kp; Yh = g_Kh; }
    else                      { X = v; W = Wv; bias = bv; Y = Vp; Yh = 0; }

    __shared__ __nv_bfloat16 Xh[128][40], Xl[128][40];   // [row][k], +8 pad
    __shared__ __nv_bfloat16 Wh[128][40], Wl[128][40];

    const int m0 = blockIdx.x * 128;
    const int n0 = blockIdx.y * 128;
    const int tid = threadIdx.x;
    const int w = tid >> 5, l = tid & 31;
    const int g = l >> 2, tg = l & 3;
    const int wm = w >> 2;
    const int wn = w & 3;
    const int lr = tid >> 1;
    const int lcb = (tid & 1) * 16;

    float acc[4][4][4];
#pragma unroll
    for (int mi = 0; mi < 4; mi++)
#pragma unroll
        for (int ni = 0; ni < 4; ni++)
#pragma unroll
            for (int j = 0; j < 4; j++) acc[mi][ni][j] = 0.f;

    for (int kt = 0; kt < DM_; kt += 32) {
        float4 xv[4], wv[4];
#pragma unroll
        for (int c = 0; c < 4; c++) {
            xv[c] = *(const float4*)&X[(size_t)(m0 + lr) * DM_ + kt + lcb + c * 4];
            wv[c] = *(const float4*)&W[(size_t)(n0 + lr) * DM_ + kt + lcb + c * 4];
        }
        __syncthreads();
#pragma unroll
        for (int c = 0; c < 4; c++) {
            const int idx = lcb + c * 4;
            float xs[4] = {xv[c].x, xv[c].y, xv[c].z, xv[c].w};
            float ws[4] = {wv[c].x, wv[c].y, wv[c].z, wv[c].w};
            __nv_bfloat16 xh[4], wh[4];
            float xr[4], wr[4];
#pragma unroll
            for (int e = 0; e < 4; e++) {
                xh[e] = __float2bfloat16(xs[e]);
                xr[e] = xs[e] - __bfloat162float(xh[e]);
                wh[e] = __float2bfloat16(ws[e]);
                wr[e] = ws[e] - __bfloat162float(wh[e]);
            }
            *(__nv_bfloat162*)&Xh[lr][idx]     = __nv_bfloat162(xh[0], xh[1]);
            *(__nv_bfloat162*)&Xh[lr][idx + 2] = __nv_bfloat162(xh[2], xh[3]);
            *(__nv_bfloat162*)&Xl[lr][idx]     = __floats2bfloat162_rn(xr[0], xr[1]);
            *(__nv_bfloat162*)&Xl[lr][idx + 2] = __floats2bfloat162_rn(xr[2], xr[3]);
            *(__nv_bfloat162*)&Wh[lr][idx]     = __nv_bfloat162(wh[0], wh[1]);
            *(__nv_bfloat162*)&Wh[lr][idx + 2] = __nv_bfloat162(wh[2], wh[3]);
            *(__nv_bfloat162*)&Wl[lr][idx]     = __floats2bfloat162_rn(wr[0], wr[1]);
            *(__nv_bfloat162*)&Wl[lr][idx + 2] = __floats2bfloat162_rn(wr[2], wr[3]);
        }
        __syncthreads();

#pragma unroll
        for (int ks = 0; ks < 2; ks++) {
            const int k0 = ks * 16;
            unsigned ah[4][4], al[4][4];
#pragma unroll
            for (int mi = 0; mi < 4; mi++) {
                const int r0 = wm * 64 + mi * 16 + g, r1 = r0 + 8;
                ah[mi][0] = *(const unsigned*)&Xh[r0][k0 + tg * 2];
                ah[mi][1] = *(const unsigned*)&Xh[r1][k0 + tg * 2];
                ah[mi][2] = *(const unsigned*)&Xh[r0][k0 + tg * 2 + 8];
                ah[mi][3] = *(const unsigned*)&Xh[r1][k0 + tg * 2 + 8];
                al[mi][0] = *(const unsigned*)&Xl[r0][k0 + tg * 2];
                al[mi][1] = *(const unsigned*)&Xl[r1][k0 + tg * 2];
                al[mi][2] = *(const unsigned*)&Xl[r0][k0 + tg * 2 + 8];
                al[mi][3] = *(const unsigned*)&Xl[r1][k0 + tg * 2 + 8];
            }
            unsigned bh[4][2], bl[4][2];
#pragma unroll
            for (int ni = 0; ni < 4; ni++) {
                const int col = wn * 32 + ni * 8 + g;
                bh[ni][0] = *(const unsigned*)&Wh[col][k0 + tg * 2];
                bh[ni][1] = *(const unsigned*)&Wh[col][k0 + tg * 2 + 8];
                bl[ni][0] = *(const unsigned*)&Wl[col][k0 + tg * 2];
                bl[ni][1] = *(const unsigned*)&Wl[col][k0 + tg * 2 + 8];
            }
#pragma unroll
            for (int mi = 0; mi < 4; mi++)
#pragma unroll
                for (int ni = 0; ni < 4; ni++) {
                    mma_bf16(acc[mi][ni], ah[mi], bh[ni]);
                    mma_bf16(acc[mi][ni], ah[mi], bl[ni]);
                    mma_bf16(acc[mi][ni], al[mi], bh[ni]);
                }
        }
    }

#pragma unroll
    for (int ni = 0; ni < 4; ni++) {
        const int col = n0 + wn * 32 + ni * 8 + tg * 2;
        const float b0 = bias[col], b1 = bias[col + 1];
#pragma unroll
        for (int mi = 0; mi < 4; mi++) {
            const int row0 = m0 + wm * 64 + mi * 16 + g, row1 = row0 + 8;
            float o00 = acc[mi][ni][0] + b0, o01 = acc[mi][ni][1] + b1;
            float o10 = acc[mi][ni][2] + b0, o11 = acc[mi][ni][3] + b1;
            *(float2*)&Y[(size_t)row0 * DM_ + col] = make_float2(o00, o01);
            *(float2*)&Y[(size_t)row1 * DM_ + col] = make_float2(o10, o11);
            if (Yh) {
                *(__nv_bfloat162*)&Yh[(size_t)row0 * DM_ + col] = __floats2bfloat162_rn(o00, o01);
                *(__nv_bfloat162*)&Yh[(size_t)row1 * DM_ + col] = __floats2bfloat162_rn(o10, o11);
            }
        }
    }

    // V branch: fill output with bo (this tile covered exactly once)
    if (blockIdx.z == 2) {
#pragma unroll
        for (int ni = 0; ni < 4; ni++) {
            const int col = n0 + wn * 32 + ni * 8 + tg * 2;
            const float2 ob = make_float2(bo[col], bo[col + 1]);
#pragma unroll
            for (int mi = 0; mi < 4; mi++) {
                const int row0 = m0 + wm * 64 + mi * 16 + g, row1 = row0 + 8;
                *(float2*)&out[(size_t)row0 * DM_ + col] = ob;
                *(float2*)&out[(size_t)row1 * DM_ + col] = ob;
            }
        }
    }
}

// =====================================================================
// KL via HMMA + ldmatrix + cp.async double-buffered K tiles
// (byte-exact R12 version: __expf epilogue).
// =====================================================================
__global__ __launch_bounds__(256) void kl_hmma_kernel()
{
    extern __shared__ __align__(16) char smraw[];
    const unsigned smb = smem_u32(smraw);
    const unsigned QSB = smb;
    const unsigned KSB0 = smb + 18432u, KSB1 = smb + 36864u;

    const int tid = threadIdx.x;
    const int w = tid >> 5, l = tid & 31;
    const int g = l >> 2, tg = l & 3;
    const int bh = blockIdx.x, b = bh >> 3, h = bh & 7;
    const int q0 = blockIdx.y * 128;
    const int kc = blockIdx.z, kbase = kc * (T_ / KC_);
    const int NT = (T_ / KC_) / 128;   // 8 key tiles

    const __nv_bfloat16* Qh = g_Qh + (size_t)(b * T_) * DM_ + h * D_;
    const __nv_bfloat16* Kh = g_Kh + (size_t)(b * T_) * DM_ + h * D_;

    const int cr = tid >> 1, chalf = tid & 1;
    const unsigned cdst_off = (unsigned)(cr * 144 + chalf * 64);

    {
        const __nv_bfloat16* src = Qh + (size_t)(q0 + cr) * DM_ + chalf * 32;
#pragma unroll
        for (int c = 0; c < 4; c++) cp16(QSB + cdst_off + c * 16, src + c * 8);
        const __nv_bfloat16* ksrc = Kh + (size_t)(kbase + cr) * DM_ + chalf * 32;
#pragma unroll
        for (int c = 0; c < 4; c++) cp16(KSB0 + cdst_off + c * 16, ksrc + c * 8);
        cp_commit();
    }
    {
        const __nv_bfloat16* ksrc = Kh + (size_t)(kbase + 128 + cr) * DM_ + chalf * 32;
#pragma unroll
        for (int c = 0; c < 4; c++) cp16(KSB1 + cdst_off + c * 16, ksrc + c * 8);
        cp_commit();
    }

    float acc[16][4];
    float Z0 = 0.f, S0 = 0.f, Z1 = 0.f, S1 = 0.f;

    const unsigned a_row_off = (unsigned)((w * 16 + (l & 15)) * 144 + ((l >> 4) << 3) * 2);
    const unsigned b_row_off = (unsigned)((((l >> 4) << 3) + (l & 7)) * 144 + (((l >> 3) & 1) << 3) * 2);

#pragma unroll
    for (int ni = 0; ni < 16; ni++)
#pragma unroll
        for (int j = 0; j < 4; j++) acc[ni][j] = 0.f;

    for (int it = 0; it < NT; it++) {
        if (it + 1 < NT) cp_wait1(); else cp_wait0();
        __syncthreads();

        const unsigned kb = (it & 1) ? KSB1 : KSB0;
#pragma unroll
        for (int ks = 0; ks < 4; ks++) {
            const unsigned k0b = (unsigned)(ks * 32);
            unsigned a[4];
            ldmx4(a[0], a[1], a[2], a[3], QSB + a_row_off + k0b);
#pragma unroll
            for (int nb = 0; nb < 8; nb++) {
                unsigned b0, b1, b2, b3;
                ldmx4(b0, b1, b2, b3, kb + b_row_off + (unsigned)(nb * 16 * 144) + k0b);
                unsigned bb0[2] = {b0, b1}, bb1[2] = {b2, b3};
                mma_bf16(acc[nb * 2],     a, bb0);
                mma_bf16(acc[nb * 2 + 1], a, bb1);
            }
        }

        // epilogue: exp-accumulate this tile's scores, reset accumulators
#pragma unroll
        for (int ni = 0; ni < 16; ni++) {
            float s0 = acc[ni][0] * 0.125f; float e0 = __expf(s0); Z0 += e0; S0 += e0 * s0;
            float s1 = acc[ni][1] * 0.125f; float e1 = __expf(s1); Z0 += e1; S0 += e1 * s1;
            float s2 = acc[ni][2] * 0.125f; float e2 = __expf(s2); Z1 += e2; S1 += e2 * s2;
            float s3 = acc[ni][3] * 0.125f; float e3 = __expf(s3); Z1 += e3; S1 += e3 * s3;
            acc[ni][0] = 0.f; acc[ni][1] = 0.f; acc[ni][2] = 0.f; acc[ni][3] = 0.f;
        }
        __syncthreads();   // buffer (it&1) fully consumed by all warps

        if (it + 2 < NT) {
            const unsigned dst = ((it & 1) ? KSB1 : KSB0) + cdst_off;
            const __nv_bfloat16* ksrc = Kh + (size_t)(kbase + (it + 2) * 128 + cr) * DM_ + chalf * 32;
#pragma unroll
            for (int c = 0; c < 4; c++) cp16(dst + c * 16, ksrc + c * 8);
            cp_commit();
        }
    }

#pragma unroll
    for (int off = 1; off < 4; off <<= 1) {
        Z0 += __shfl_xor_sync(0xffffffffu, Z0, off);
        S0 += __shfl_xor_sync(0xffffffffu, S0, off);
        Z1 += __shfl_xor_sync(0xffffffffu, Z1, off);
        S1 += __shfl_xor_sync(0xffffffffu, S1, off);
    }
    if (tg == 0) {
        const int base = (kc * BH_ + bh) * T_ + q0 + w * 16 + g;
        g_Zp[base]     = Z0;  g_Sp[base]     = S0;
        g_Zp[base + 8] = Z1;  g_Sp[base + 8] = S1;
    }
}

// =====================================================================
// Top-3 per (b,h), single pass: per-thread top-3 of 8 elems, 5 shfl
// merge rounds per warp, one smem stage, serial merge of 8 lists.
// =====================================================================
__global__ __launch_bounds__(256) void topk_kernel()
{
    __shared__ float swv[8][3];
    __shared__ int   swi[8][3];
    const int bh = blockIdx.x;
    const int tid = threadIdx.x;
    const int lane = tid & 31, warp = tid >> 5;
    const float LOGU = logf(1.0f / (float)T_ + 1e-10f);

    float v[3] = {-1e30f, -1e30f, -1e30f};
    int ix[3] = {T_, T_, T_};
#pragma unroll
    for (int kk = 0; kk < 8; kk++) {
        const int i = kk * 256 + tid;
        float z = g_Zp[bh * T_ + i] + g_Zp[(BH_ + bh) * T_ + i];
        float s = g_Sp[bh * T_ + i] + g_Sp[(BH_ + bh) * T_ + i];
        float kl = s / z - __logf(z) - LOGU;
        ins3(v, ix, kl, i);
    }
#pragma unroll
    for (int off = 16; off > 0; off >>= 1) {
        float ov[3]; int oix[3];
#pragma unroll
        for (int j = 0; j < 3; j++) {
            ov[j]  = __shfl_xor_sync(0xffffffffu, v[j], off);
            oix[j] = __shfl_xor_sync(0xffffffffu, ix[j], off);
        }
#pragma unroll
        for (int j = 0; j < 3; j++) ins3(v, ix, ov[j], oix[j]);
    }
    if (lane == 0) {
#pragma unroll
        for (int j = 0; j < 3; j++) { swv[warp][j] = v[j]; swi[warp][j] = ix[j]; }
    }
    __syncthreads();
    if (tid == 0) {
        float bv[3] = {-1e30f, -1e30f, -1e30f};
        int bix[3] = {T_, T_, T_};
        for (int wq = 0; wq < 8; wq++)
#pragma unroll
            for (int j = 0; j < 3; j++) ins3(bv, bix, swv[wq][j], swi[wq][j]);
#pragma unroll
        for (int r = 0; r < U_; r++) g_top[bh * U_ + r] = bix[r];
    }
}

// =====================================================================
// Reduced attention (fp32 path): grid (48, NCH_).
// =====================================================================
__global__ __launch_bounds__(256) void sparse_attn_kernel()
{
    __shared__ float qs[64];
    __shared__ float e[256];
    __shared__ float red[8];
    __shared__ float pb[4][64];

    const int bid = blockIdx.x;
    const int ch  = blockIdx.y;
    const int bh = bid / U_;
    const int b = bh >> 3, h = bh & 7;
    const int t = g_top[bid];
    const int tid = threadIdx.x;
    const int warp = tid >> 5, lane = tid & 31;

    const float* Qb = g_Q + ((size_t)(b * T_) + t) * DM_ + h * D_;
    if (tid < 16) *(float4*)&qs[tid * 4] = *(const float4*)&Qb[tid * 4];
    __syncthreads();

    const int kk = ch * 256 + tid;
    const float* Krow = g_K + ((size_t)(b * T_) + kk) * DM_ + h * D_;
    float dot = 0.f;
#pragma unroll
    for (int i = 0; i < 16; i++) {
        float4 kv = *(const float4*)&Krow[i * 4];
        float4 qv = *(const float4*)&qs[i * 4];
        dot += kv.x * qv.x + kv.y * qv.y + kv.z * qv.z + kv.w * qv.w;
    }
    float s = dot * 0.125f;
    if (!(s == s)) s = -10000.f;
    s = fminf(fmaxf(s, -10000.f), 10000.f);
    float ev = expf(s);
    e[tid] = ev;

    float zr = ev;
#pragma unroll
    for (int off = 16; off > 0; off >>= 1) zr += __shfl_xor_sync(0xffffffffu, zr, off);
    if (lane == 0) red[warp] = zr;
    __syncthreads();
    if (tid == 0) {
        float z = 0.f;
        for (int w = 0; w < 8; w++) z += red[w];
        g_zc[bid * NCH_ + ch] = z;
    }

    const int d = tid & 63, c = tid >> 6;
    const float* Vb = g_V + ((size_t)(b * T_) + ch * 256 + c * 64) * DM_ + h * D_ + d;
    float o = 0.f;
#pragma unroll 8
    for (int j = 0; j < 64; j++) o += e[c * 64 + j] * Vb[(size_t)j * DM_];
    pb[c][d] = o;
    __syncthreads();
    if (tid < 64)
        g_attp[(bid * NCH_ + ch) * D_ + tid] =
            pb[0][tid] + pb[1][tid] + pb[2][tid] + pb[3][tid];
}

// =====================================================================
// Scatter: add the 48 selected-row contributions (out pre-filled with
// bo by proj3's V branch).
// =====================================================================
__global__ __launch_bounds__(512) void scatter_kernel(
    const float* __restrict__ Wo, float* __restrict__ out)
{
    __shared__ float att[64];
    const int bid = blockIdx.x;
    const int bh = bid / U_;
    const int b = bh >> 3, h = bh & 7;
    const int t = g_top[bid];
    const int j = threadIdx.x;
    if (j < 64) {
        float z = 0.f, o = 0.f;
#pragma unroll
        for (int c = 0; c < NCH_; c++) {
            z += g_zc[bid * NCH_ + c];
            o += g_attp[(bid * NCH_ + c) * D_ + j];
        }
        att[j] = o / z;
    }
    __syncthreads();
    const float* w = Wo + (size_t)j * DM_ + h * D_;
    float a = 0.f;
#pragma unroll
    for (int d = 0; d < 64; d++) a += att[d] * w[d];
    atomicAdd(&out[((size_t)b * T_ + t) * DM_ + j], a);
}

// =====================================================================
extern "C" void kernel_launch(void* const* d_in, const int* in_sizes, int n_in,
                              void* d_out, int out_size)
{
    const float* query = (const float*)d_in[0];
    const float* key   = (const float*)d_in[1];
    const float* value = (const float*)d_in[2];
    const float* Wq    = (const float*)d_in[3];
    const float* bq    = (const float*)d_in[4];
    const float* Wk    = (const float*)d_in[5];
    const float* bk    = (const float*)d_in[6];
    const float* Wv    = (const float*)d_in[7];
    const float* bv    = (const float*)d_in[8];
    const float* Wo    = (const float*)d_in[9];
    const float* bo    = (const float*)d_in[10];
    float* out = (float*)d_out;

    float *Qp, *Kp, *Vp;
    cudaGetSymbolAddress((void**)&Qp, g_Q);
    cudaGetSymbolAddress((void**)&Kp, g_K);
    cudaGetSymbolAddress((void**)&Vp, g_V);

    const int KL_SMEM = 3 * 18432;  // 55296
    cudaFuncSetAttribute(kl_hmma_kernel, cudaFuncAttributeMaxDynamicSharedMemorySize, KL_SMEM);

    dim3 pg(32, 4, 3);
    proj3_kernel<<<pg, 256>>>(query, key, value, Wq, Wk, Wv, bq, bk, bv,
                              Qp, Kp, Vp, bo, out);

    dim3 kg(BH_, T_ / 128, KC_);  // (16, 16, 2)
    kl_hmma_kernel<<<kg, 256, KL_SMEM>>>();

    topk_kernel<<<BH_, 256>>>();

    dim3 sg(BH_ * U_, NCH_);
    sparse_attn_kernel<<<sg, 256>>>();

    scatter_kernel<<<BH_ * U_, 512>>>(Wo, out);
}